// round 1
// baseline (speedup 1.0000x reference)
#include <cuda_runtime.h>

// InterfaceBoundaryLoss: B=4, H=W=2048, DX=DY=0.01, E_IN=2, CONST=1, WEIGHT=1.
//
// boundary/interface masks are deterministic functions of (h,w):
//   dd = (h-1024)^2 + (w-1024)^2   (exact integer)
//   interface  <=> dd <  262144          (r < 512)
//   boundary   <=> 261122 <= dd <= 263168 (511 < r < 513)
// (float64 sqrt rounding cannot cross these thresholds; verified analytically)
//
// All five loss terms are masked by `boundary` and share denominator B*nb,
// so we only visit the ~12.8K annulus pixels inside the [512,1536]^2 box.

#define HH 2048
#define WW 2048
#define HWSZ (HH * WW)

__device__ double       g_acc  = 0.0;
__device__ unsigned int g_nb   = 0u;
__device__ unsigned int g_done = 0u;

__global__ void __launch_bounds__(256)
ibl_kernel(const float* __restrict__ s1, const float* __restrict__ s2,
           float* __restrict__ out, unsigned int nblocks)
{
    const int tid = threadIdx.x;
    const int h = 512 + blockIdx.y;
    const int w = 512 + blockIdx.x * 256 + tid;

    double lacc = 0.0;
    unsigned int lcnt = 0u;

    if (w <= 1536) {
        const int a  = h - 1024;
        const int b  = w - 1024;
        const int dd = a * a + b * b;
        if (dd >= 261122 && dd <= 263168) {       // boundary pixel
            lcnt = 1u;
            const bool c  = dd < 262144;          // interface at (h,w)
            const bool iu = ((a - 1) * (a - 1) + b * b) < 262144;
            const bool id = ((a + 1) * (a + 1) + b * b) < 262144;
            const bool il = (a * a + (b - 1) * (b - 1)) < 262144;
            const bool ir = (a * a + (b + 1) * (b + 1)) < 262144;
            // mask == m_up etc.; identical for ~interface (negation preserves ==)
            const bool pu = (iu == c);
            const bool pd = (id == c);
            const bool pl = (il == c);
            const bool pr = (ir == c);
            // offset 0 -> neighbor == center -> gradient exactly 0
            const int voff = pu ? -WW : (pd ? WW : 0);
            const int hoff = pl ? -1  : (pr ? 1  : 0);

            const int idx0 = h * WW + w;
            float facc = 0.0f;
            #pragma unroll
            for (int bb = 0; bb < 4; ++bb) {
                const float* p1 = s1 + idx0 + bb * HWSZ;
                const float* p2 = s2 + idx0 + bb * HWSZ;
                const float o1 = __ldg(p1);
                const float o2 = __ldg(p2);
                const float dv = o1 - o2;
                facc += dv * dv;

                float g, t;
                g = (o1 - __ldg(p1 + voff)) * 100.0f;  // gx1 = (o - o_nb)/DX
                t = fmaf(2.0f, g, -1.0f);  facc += t * t;
                g = (o1 - __ldg(p1 + hoff)) * 100.0f;  // gy1
                t = fmaf(2.0f, g, -1.0f);  facc += t * t;
                g = (o2 - __ldg(p2 + voff)) * 100.0f;  // gx2
                t = fmaf(2.0f, g, -1.0f);  facc += t * t;
                g = (o2 - __ldg(p2 + hoff)) * 100.0f;  // gy2
                t = fmaf(2.0f, g, -1.0f);  facc += t * t;
            }
            lacc = (double)facc;
        }
    }

    // ---- block reduction (double sum + boundary-pixel count) ----
    #pragma unroll
    for (int o = 16; o > 0; o >>= 1) {
        lacc += __shfl_down_sync(0xffffffffu, lacc, o);
        lcnt += __shfl_down_sync(0xffffffffu, lcnt, o);
    }
    __shared__ double       sacc[8];
    __shared__ unsigned int scnt[8];
    const int wid  = tid >> 5;
    const int lane = tid & 31;
    if (lane == 0) { sacc[wid] = lacc; scnt[wid] = lcnt; }
    __syncthreads();
    if (wid == 0) {
        lacc = (lane < 8) ? sacc[lane] : 0.0;
        lcnt = (lane < 8) ? scnt[lane] : 0u;
        #pragma unroll
        for (int o = 4; o > 0; o >>= 1) {
            lacc += __shfl_down_sync(0xffffffffu, lacc, o);
            lcnt += __shfl_down_sync(0xffffffffu, lcnt, o);
        }
        if (lane == 0) {
            if (lacc != 0.0) atomicAdd(&g_acc, lacc);
            if (lcnt != 0u)  atomicAdd(&g_nb, lcnt);
            __threadfence();
            // ticket; atomicInc wraps g_done back to 0 on the last block
            const unsigned int old = atomicInc(&g_done, nblocks - 1u);
            if (old == nblocks - 1u) {
                const double       tot = atomicAdd(&g_acc, 0.0);
                const unsigned int nb  = atomicAdd(&g_nb, 0u);
                out[0] = (float)(tot / (4.0 * (double)nb));
                // reset for the next graph replay
                g_acc = 0.0;
                g_nb  = 0u;
                __threadfence();
            }
        }
    }
}

extern "C" void kernel_launch(void* const* d_in, const int* in_sizes, int n_in,
                              void* d_out, int out_size)
{
    (void)in_sizes; (void)n_in; (void)out_size;
    const float* s1 = (const float*)d_in[0];
    const float* s2 = (const float*)d_in[1];
    float* out = (float*)d_out;

    dim3 grid(5, 1025);            // covers w,h in [512, 1536] (1025 x 1025 box)
    const unsigned int nblocks = 5u * 1025u;
    ibl_kernel<<<grid, 256>>>(s1, s2, out, nblocks);
}

// round 2
// speedup vs baseline: 1.8045x; 1.8045x over previous
#include <cuda_runtime.h>

// InterfaceBoundaryLoss: B=4, H=W=2048, DX=DY=0.01, E_IN=2, CONST=1, WEIGHT=1.
//
// Masks are deterministic in (h,w): with a=h-1024, b=w-1024, dd=a^2+b^2:
//   interface <=> dd <  262144           (r < 512)
//   boundary  <=> 261122 <= dd <= 263168 (|r-512| < 1)
// Only boundary pixels contribute. Rows with pixels: |a| <= 512.
// Per row: b^2 in [max(0,261122-a^2), 263168-a^2]  -> two mirrored intervals.
// One warp per row enumerates its interval directly (~12.8K pixels total).

#define WW 2048
#define HWSZ (2048 * 2048)
#define NROWS 1025            // a in [-512, 512]
#define WARPS_PER_BLK 8
#define NBLOCKS ((NROWS + WARPS_PER_BLK - 1) / WARPS_PER_BLK)   // 129

__device__ double       g_acc  = 0.0;
__device__ unsigned int g_nb   = 0u;
__device__ unsigned int g_done = 0u;

__device__ __forceinline__ float pixel_loss(const float* __restrict__ s1,
                                            const float* __restrict__ s2,
                                            int a, int b)
{
    const int dd = a * a + b * b;
    const bool c  = dd < 262144;
    const bool pu = ((((a - 1) * (a - 1) + b * b) < 262144) == c);
    const bool pd = ((((a + 1) * (a + 1) + b * b) < 262144) == c);
    const bool pl = (((a * a + (b - 1) * (b - 1)) < 262144) == c);
    const bool pr = (((a * a + (b + 1) * (b + 1)) < 262144) == c);
    const int voff = pu ? -WW : (pd ? WW : 0);   // 0 -> gradient exactly 0
    const int hoff = pl ? -1  : (pr ? 1  : 0);

    const int idx0 = (a + 1024) * WW + (b + 1024);
    float facc = 0.0f;
    #pragma unroll
    for (int bb = 0; bb < 4; ++bb) {
        const float* p1 = s1 + idx0 + bb * HWSZ;
        const float* p2 = s2 + idx0 + bb * HWSZ;
        const float o1 = __ldg(p1);
        const float o2 = __ldg(p2);
        const float dv = o1 - o2;
        facc = fmaf(dv, dv, facc);
        float g, t;
        g = (o1 - __ldg(p1 + voff)) * 100.0f;                 // gx1
        t = fmaf(2.0f, g, -1.0f);  facc = fmaf(t, t, facc);
        g = (o1 - __ldg(p1 + hoff)) * 100.0f;                 // gy1
        t = fmaf(2.0f, g, -1.0f);  facc = fmaf(t, t, facc);
        g = (o2 - __ldg(p2 + voff)) * 100.0f;                 // gx2
        t = fmaf(2.0f, g, -1.0f);  facc = fmaf(t, t, facc);
        g = (o2 - __ldg(p2 + hoff)) * 100.0f;                 // gy2
        t = fmaf(2.0f, g, -1.0f);  facc = fmaf(t, t, facc);
    }
    return facc;
}

__global__ void __launch_bounds__(WARPS_PER_BLK * 32)
ibl_kernel(const float* __restrict__ s1, const float* __restrict__ s2,
           float* __restrict__ out)
{
    const int tid   = threadIdx.x;
    const int lane  = tid & 31;
    const int wid   = tid >> 5;
    const int gwarp = blockIdx.x * WARPS_PER_BLK + wid;

    double lacc = 0.0;
    unsigned int lcnt = 0u;

    if (gwarp < NROWS) {
        const int a  = gwarp - 512;
        const int lo = 261122 - a * a;          // may be <= 0 (a = +-512)
        const int hi = 263168 - a * a;          // >= 1024 for all valid rows

        // bmax = floor(sqrt(hi)); bmin = ceil(sqrt(max(lo,0))); exact fixup
        int bmax = (int)sqrt((double)hi);
        while ((bmax + 1) * (bmax + 1) <= hi) ++bmax;
        while (bmax * bmax > hi) --bmax;
        int bmin = 0;
        if (lo > 0) {
            bmin = (int)sqrt((double)lo);
            while (bmin * bmin < lo) ++bmin;
            while (bmin > 0 && (bmin - 1) * (bmin - 1) >= lo) --bmin;
        }

        if (bmax >= bmin) {
            if (lane == 0)
                lcnt = (bmin > 0) ? 2u * (unsigned)(bmax - bmin + 1)
                                  : (unsigned)(2 * bmax + 1);
            for (int b = bmin + lane; b <= bmax; b += 32) {
                float f = pixel_loss(s1, s2, a, b);
                if (b != 0) f += pixel_loss(s1, s2, a, -b);
                lacc += (double)f;
            }
        }
    }

    // ---- warp reduce ----
    #pragma unroll
    for (int o = 16; o > 0; o >>= 1) {
        lacc += __shfl_down_sync(0xffffffffu, lacc, o);
        lcnt += __shfl_down_sync(0xffffffffu, lcnt, o);
    }
    __shared__ double       sacc[WARPS_PER_BLK];
    __shared__ unsigned int scnt[WARPS_PER_BLK];
    if (lane == 0) { sacc[wid] = lacc; scnt[wid] = lcnt; }
    __syncthreads();
    if (wid == 0) {
        lacc = (lane < WARPS_PER_BLK) ? sacc[lane] : 0.0;
        lcnt = (lane < WARPS_PER_BLK) ? scnt[lane] : 0u;
        #pragma unroll
        for (int o = WARPS_PER_BLK / 2; o > 0; o >>= 1) {
            lacc += __shfl_down_sync(0xffffffffu, lacc, o);
            lcnt += __shfl_down_sync(0xffffffffu, lcnt, o);
        }
        if (lane == 0) {
            atomicAdd(&g_acc, lacc);
            atomicAdd(&g_nb, lcnt);
            __threadfence();
            const unsigned int old = atomicInc(&g_done, NBLOCKS - 1u);
            if (old == NBLOCKS - 1u) {       // last block finalizes + resets
                const double       tot = atomicAdd(&g_acc, 0.0);
                const unsigned int nb  = atomicAdd(&g_nb, 0u);
                out[0] = (float)(tot / (4.0 * (double)nb));
                g_acc = 0.0;
                g_nb  = 0u;
                __threadfence();
            }
        }
    }
}

extern "C" void kernel_launch(void* const* d_in, const int* in_sizes, int n_in,
                              void* d_out, int out_size)
{
    (void)in_sizes; (void)n_in; (void)out_size;
    const float* s1 = (const float*)d_in[0];
    const float* s2 = (const float*)d_in[1];
    float* out = (float*)d_out;
    ibl_kernel<<<NBLOCKS, WARPS_PER_BLK * 32>>>(s1, s2, out);
}

// round 3
// speedup vs baseline: 2.0930x; 1.1599x over previous
#include <cuda_runtime.h>

// InterfaceBoundaryLoss: B=4, H=W=2048, DX=DY=0.01, E_IN=2, CONST=1, WEIGHT=1.
//
// Masks are deterministic in (h,w): with a=h-1024, b=w-1024, dd=a^2+b^2:
//   interface <=> dd <  262144           (r < 512)
//   boundary  <=> 261122 <= dd <= 263168 (|r-512| < 1)
// Only boundary pixels contribute. One warp per row a in [-512,512]; per row
// b^2 in [max(0,261122-a^2), 263168-a^2] gives two mirrored intervals.
// R3: all-FP32 hot path (no double sqrt / double reduction — FP64 pipe was
// the hidden bottleneck in R2).

#define WW 2048
#define HWSZ (2048 * 2048)
#define NROWS 1025
#define WARPS_PER_BLK 8
#define NBLOCKS ((NROWS + WARPS_PER_BLK - 1) / WARPS_PER_BLK)   // 129

__device__ double       g_acc  = 0.0;
__device__ unsigned int g_nb   = 0u;
__device__ unsigned int g_done = 0u;

__device__ __forceinline__ float pixel_loss(const float* __restrict__ s1,
                                            const float* __restrict__ s2,
                                            int a, int b)
{
    const int dd = a * a + b * b;
    const bool c  = dd < 262144;
    const bool pu = ((((a - 1) * (a - 1) + b * b) < 262144) == c);
    const bool pd = ((((a + 1) * (a + 1) + b * b) < 262144) == c);
    const bool pl = (((a * a + (b - 1) * (b - 1)) < 262144) == c);
    const bool pr = (((a * a + (b + 1) * (b + 1)) < 262144) == c);
    const int voff = pu ? -WW : (pd ? WW : 0);   // 0 -> gradient exactly 0
    const int hoff = pl ? -1  : (pr ? 1  : 0);

    const int idx0 = (a + 1024) * WW + (b + 1024);
    float facc = 0.0f;
    #pragma unroll
    for (int bb = 0; bb < 4; ++bb) {
        const float* p1 = s1 + idx0 + bb * HWSZ;
        const float* p2 = s2 + idx0 + bb * HWSZ;
        const float o1 = __ldg(p1);
        const float o2 = __ldg(p2);
        const float dv = o1 - o2;
        facc = fmaf(dv, dv, facc);
        float g, t;
        g = (o1 - __ldg(p1 + voff)) * 100.0f;                 // gx1
        t = fmaf(2.0f, g, -1.0f);  facc = fmaf(t, t, facc);
        g = (o1 - __ldg(p1 + hoff)) * 100.0f;                 // gy1
        t = fmaf(2.0f, g, -1.0f);  facc = fmaf(t, t, facc);
        g = (o2 - __ldg(p2 + voff)) * 100.0f;                 // gx2
        t = fmaf(2.0f, g, -1.0f);  facc = fmaf(t, t, facc);
        g = (o2 - __ldg(p2 + hoff)) * 100.0f;                 // gy2
        t = fmaf(2.0f, g, -1.0f);  facc = fmaf(t, t, facc);
    }
    return facc;
}

__global__ void __launch_bounds__(WARPS_PER_BLK * 32)
ibl_kernel(const float* __restrict__ s1, const float* __restrict__ s2,
           float* __restrict__ out)
{
    const int tid   = threadIdx.x;
    const int lane  = tid & 31;
    const int wid   = tid >> 5;
    const int gwarp = blockIdx.x * WARPS_PER_BLK + wid;

    float lacc = 0.0f;
    unsigned int lcnt = 0u;

    if (gwarp < NROWS) {
        const int a  = gwarp - 512;
        const int lo = 261122 - a * a;          // may be <= 0 (a = +-512)
        const int hi = 263168 - a * a;          // >= 1024 for all valid rows

        // floor/ceil integer sqrt via FP32 + exact integer fixup
        int bmax = (int)sqrtf((float)hi);
        while ((bmax + 1) * (bmax + 1) <= hi) ++bmax;
        while (bmax * bmax > hi) --bmax;
        int bmin = 0;
        if (lo > 0) {
            bmin = (int)sqrtf((float)lo);
            while (bmin * bmin < lo) ++bmin;
            while (bmin > 0 && (bmin - 1) * (bmin - 1) >= lo) --bmin;
        }

        if (bmax >= bmin) {
            if (lane == 0)
                lcnt = (bmin > 0) ? 2u * (unsigned)(bmax - bmin + 1)
                                  : (unsigned)(2 * bmax + 1);
            for (int b = bmin + lane; b <= bmax; b += 32) {
                float f = pixel_loss(s1, s2, a, b);
                if (b != 0) f += pixel_loss(s1, s2, a, -b);
                lacc += f;
            }
        }
    }

    // ---- warp reduce (float sum + count) ----
    #pragma unroll
    for (int o = 16; o > 0; o >>= 1) {
        lacc += __shfl_down_sync(0xffffffffu, lacc, o);
        lcnt += __shfl_down_sync(0xffffffffu, lcnt, o);
    }
    __shared__ float        sacc[WARPS_PER_BLK];
    __shared__ unsigned int scnt[WARPS_PER_BLK];
    if (lane == 0) { sacc[wid] = lacc; scnt[wid] = lcnt; }
    __syncthreads();
    if (wid == 0) {
        lacc = (lane < WARPS_PER_BLK) ? sacc[lane] : 0.0f;
        lcnt = (lane < WARPS_PER_BLK) ? scnt[lane] : 0u;
        #pragma unroll
        for (int o = WARPS_PER_BLK / 2; o > 0; o >>= 1) {
            lacc += __shfl_down_sync(0xffffffffu, lacc, o);
            lcnt += __shfl_down_sync(0xffffffffu, lcnt, o);
        }
        if (lane == 0) {
            atomicAdd(&g_acc, (double)lacc);   // one FP64 atomic per block
            atomicAdd(&g_nb, lcnt);
            __threadfence();
            const unsigned int old = atomicInc(&g_done, NBLOCKS - 1u);
            if (old == NBLOCKS - 1u) {         // last block finalizes + resets
                const double       tot = atomicAdd(&g_acc, 0.0);
                const unsigned int nb  = atomicAdd(&g_nb, 0u);
                out[0] = (float)(tot / (4.0 * (double)nb));
                g_acc = 0.0;
                g_nb  = 0u;
                __threadfence();
            }
        }
    }
}

extern "C" void kernel_launch(void* const* d_in, const int* in_sizes, int n_in,
                              void* d_out, int out_size)
{
    (void)in_sizes; (void)n_in; (void)out_size;
    const float* s1 = (const float*)d_in[0];
    const float* s2 = (const float*)d_in[1];
    float* out = (float*)d_out;
    ibl_kernel<<<NBLOCKS, WARPS_PER_BLK * 32>>>(s1, s2, out);
}

// round 4
// speedup vs baseline: 2.0991x; 1.0029x over previous
#include <cuda_runtime.h>

// InterfaceBoundaryLoss: B=4, H=W=2048, DX=DY=0.01, E_IN=2, CONST=1, WEIGHT=1.
//
// Masks are deterministic in (h,w): with a=h-1024, b=w-1024, dd=a^2+b^2:
//   interface <=> dd <  262144           (r < 512)
//   boundary  <=> 261122 <= dd <= 263168 (|r-512| < 1)
// One warp per row a in [-512,512]. R4: flatten (pixel x batch) across all
// 32 lanes (R3 left 28/32 lanes idle -> pure latency serialization).

#define WW 2048
#define HWSZ (2048 * 2048)
#define NROWS 1025
#define WARPS_PER_BLK 8
#define NBLOCKS ((NROWS + WARPS_PER_BLK - 1) / WARPS_PER_BLK)   // 129

__device__ double       g_acc  = 0.0;
__device__ unsigned int g_nb   = 0u;
__device__ unsigned int g_done = 0u;

__global__ void __launch_bounds__(WARPS_PER_BLK * 32)
ibl_kernel(const float* __restrict__ s1, const float* __restrict__ s2,
           float* __restrict__ out)
{
    const int tid   = threadIdx.x;
    const int lane  = tid & 31;
    const int wid   = tid >> 5;
    const int gwarp = blockIdx.x * WARPS_PER_BLK + wid;

    float lacc = 0.0f;
    unsigned int lcnt = 0u;

    if (gwarp < NROWS) {
        const int a  = gwarp - 512;
        const int lo = 261122 - a * a;          // may be <= 0 (a = +-512)
        const int hi = 263168 - a * a;

        // floor/ceil integer sqrt via FP32 + exact integer fixup
        int bmax = (int)sqrtf((float)hi);
        while ((bmax + 1) * (bmax + 1) <= hi) ++bmax;
        while (bmax * bmax > hi) --bmax;
        int bmin = 0;
        if (lo > 0) {
            bmin = (int)sqrtf((float)lo);
            while (bmin * bmin < lo) ++bmin;
            while (bmin > 0 && (bmin - 1) * (bmin - 1) >= lo) --bmin;
        }

        if (bmax >= bmin) {
            const int Wd   = bmax - bmin + 1;               // width per side
            const int npix = (bmin > 0) ? 2 * Wd : (2 * bmax + 1);
            if (lane == 0) lcnt = (unsigned)npix;

            const int row   = a + 1024;
            const int items = npix * 4;                     // pixel x batch
            const int np2   = npix * 2;
            const int np3   = npix * 3;

            for (int i = lane; i < items; i += 32) {
                // bb = i / npix, p = i % npix  (npix <= 131; branchless-ish)
                int bb = 0, p = i;
                if (p >= np2) { bb = 2; p -= np2; }
                if (p >= npix - (bb ? -npix : 0)) {}        // (no-op guard)
                if (bb == 2) { if (p >= npix) { bb = 3; p -= npix; } }
                else         { if (p >= npix) { bb = 1; p -= npix; } }

                const int b = (bmin > 0)
                            ? ((p < Wd) ? bmin + p : -(bmin + (p - Wd)))
                            : p - bmax;

                // neighbor selection (same for both subdomains)
                const int dd = a * a + b * b;
                const bool c  = dd < 262144;
                const bool pu = ((((a - 1) * (a - 1) + b * b) < 262144) == c);
                const bool pd = ((((a + 1) * (a + 1) + b * b) < 262144) == c);
                const bool pl = (((a * a + (b - 1) * (b - 1)) < 262144) == c);
                const bool pr = (((a * a + (b + 1) * (b + 1)) < 262144) == c);
                const int voff = pu ? -WW : (pd ? WW : 0);  // 0 -> grad = 0
                const int hoff = pl ? -1  : (pr ? 1  : 0);

                const int idx = row * WW + (b + 1024) + bb * HWSZ;
                const float o1  = __ldg(s1 + idx);
                const float o1v = __ldg(s1 + idx + voff);
                const float o1h = __ldg(s1 + idx + hoff);
                const float o2  = __ldg(s2 + idx);
                const float o2v = __ldg(s2 + idx + voff);
                const float o2h = __ldg(s2 + idx + hoff);

                const float dv = o1 - o2;
                lacc = fmaf(dv, dv, lacc);
                float g, t;
                g = (o1 - o1v) * 100.0f;  t = fmaf(2.0f, g, -1.0f);
                lacc = fmaf(t, t, lacc);
                g = (o1 - o1h) * 100.0f;  t = fmaf(2.0f, g, -1.0f);
                lacc = fmaf(t, t, lacc);
                g = (o2 - o2v) * 100.0f;  t = fmaf(2.0f, g, -1.0f);
                lacc = fmaf(t, t, lacc);
                g = (o2 - o2h) * 100.0f;  t = fmaf(2.0f, g, -1.0f);
                lacc = fmaf(t, t, lacc);
            }
        }
    }

    // ---- warp reduce (float sum + count) ----
    #pragma unroll
    for (int o = 16; o > 0; o >>= 1) {
        lacc += __shfl_down_sync(0xffffffffu, lacc, o);
        lcnt += __shfl_down_sync(0xffffffffu, lcnt, o);
    }
    __shared__ float        sacc[WARPS_PER_BLK];
    __shared__ unsigned int scnt[WARPS_PER_BLK];
    if (lane == 0) { sacc[wid] = lacc; scnt[wid] = lcnt; }
    __syncthreads();
    if (wid == 0) {
        lacc = (lane < WARPS_PER_BLK) ? sacc[lane] : 0.0f;
        lcnt = (lane < WARPS_PER_BLK) ? scnt[lane] : 0u;
        #pragma unroll
        for (int o = WARPS_PER_BLK / 2; o > 0; o >>= 1) {
            lacc += __shfl_down_sync(0xffffffffu, lacc, o);
            lcnt += __shfl_down_sync(0xffffffffu, lcnt, o);
        }
        if (lane == 0) {
            atomicAdd(&g_acc, (double)lacc);
            atomicAdd(&g_nb, lcnt);
            __threadfence();
            const unsigned int old = atomicInc(&g_done, NBLOCKS - 1u);
            if (old == NBLOCKS - 1u) {         // last block finalizes + resets
                const double       tot = atomicAdd(&g_acc, 0.0);
                const unsigned int nb  = atomicAdd(&g_nb, 0u);
                out[0] = (float)(tot / (4.0 * (double)nb));
                g_acc = 0.0;
                g_nb  = 0u;
                __threadfence();
            }
        }
    }
}

extern "C" void kernel_launch(void* const* d_in, const int* in_sizes, int n_in,
                              void* d_out, int out_size)
{
    (void)in_sizes; (void)n_in; (void)out_size;
    const float* s1 = (const float*)d_in[0];
    const float* s2 = (const float*)d_in[1];
    float* out = (float*)d_out;
    ibl_kernel<<<NBLOCKS, WARPS_PER_BLK * 32>>>(s1, s2, out);
}

// round 6
// speedup vs baseline: 2.5806x; 1.2294x over previous
#include <cuda_runtime.h>

// InterfaceBoundaryLoss: B=4, H=W=2048, DX=DY=0.01, E_IN=2, CONST=1, WEIGHT=1.
//
// With a=h-1024, b=w-1024, dd=a^2+b^2:
//   interface <=> dd <  262144           (r < 512)
//   boundary  <=> 261122 <= dd <= 263168 (|r-512| < 1)
//
// R5: 8-fold symmetry. Enumerate only octant 0 <= a <= b (rows a=0..362,
// b-interval width <= 3). Each octant pixel -> 8 reflections x 4 batches =
// 32 items = one warp-wide batch. Fixed unroll-4 branchless body batches all
// loads into one latency round (R4's tail warps serialized ~12 rounds).

#define WW 2048
#define HWSZ (2048 * 2048)
#define TH  262144
#define LOQ 261122
#define HIQ 263168
#define NROWS 363              // octant rows a in [0, 362]
#define WARPS_PER_BLK 4
#define NBLOCKS ((NROWS + WARPS_PER_BLK - 1) / WARPS_PER_BLK)   // 91

__device__ double       g_acc  = 0.0;
__device__ unsigned int g_nb   = 0u;
__device__ unsigned int g_done = 0u;

__global__ void __launch_bounds__(WARPS_PER_BLK * 32)
ibl_kernel(const float* __restrict__ s1, const float* __restrict__ s2,
           float* __restrict__ out)
{
    const int tid  = threadIdx.x;
    const int lane = tid & 31;
    const int wid  = tid >> 5;
    const int a    = blockIdx.x * WARPS_PER_BLK + wid;   // octant row

    float lacc = 0.0f;
    unsigned int lcnt = 0u;

    if (a < NROWS) {
        const int lo = LOQ - a * a;            // > 0 for a <= 362
        const int hi = HIQ - a * a;

        // bmax = floor(sqrt(hi)), bminr = ceil(sqrt(lo)); FP32 + exact fixup
        int bmax = (int)sqrtf((float)hi);
        while ((bmax + 1) * (bmax + 1) <= hi) ++bmax;
        while (bmax * bmax > hi) --bmax;
        int bminr = (int)sqrtf((float)lo);
        while (bminr * bminr < lo) ++bminr;
        while ((bminr - 1) * (bminr - 1) >= lo) --bminr;
        const int bmin = (bminr > a) ? bminr : a;   // octant: b >= a
        const int Wd   = bmax - bmin + 1;           // 1..3 (4th slot = safety)

        const int refl = lane & 7;
        const int bb   = lane >> 3;                 // batch 0..3
        const int sg1  = (refl & 1) ? -1 : 1;
        const int sg2  = (refl & 2) ? -1 : 1;
        const int sw   = refl >> 2;

        const int planeoff = bb * HWSZ;

        #pragma unroll
        for (int p = 0; p < 4; ++p) {
            const int b = bmin + p;
            // duplicate-free reflection mask
            bool nodup;
            if (a == 0)       nodup = sw ? (sg2 > 0) : (sg1 > 0);
            else if (a == b)  nodup = (sw == 0);
            else              nodup = true;
            const bool act = (p < Wd) && nodup;
            const float w  = act ? 1.0f : 0.0f;

            const int x0 = sw ? b : a;
            const int y0 = sw ? a : b;
            const int x  = sg1 * x0;               // h - 1024
            const int y  = sg2 * y0;               // w - 1024

            const int dd = x * x + y * y;
            const bool c  = dd < TH;
            const bool pu = ((((x - 1) * (x - 1) + y * y) < TH) == c);
            const bool pd = ((((x + 1) * (x + 1) + y * y) < TH) == c);
            const bool pl = (((x * x + (y - 1) * (y - 1)) < TH) == c);
            const bool pr = (((x * x + (y + 1) * (y + 1)) < TH) == c);
            const int voff = pu ? -WW : (pd ? WW : 0);   // 0 -> grad = 0
            const int hoff = pl ? -1  : (pr ? 1  : 0);

            const int idx = (x + 1024) * WW + (y + 1024) + planeoff;
            const float o1  = __ldg(s1 + idx);
            const float o1v = __ldg(s1 + idx + voff);
            const float o1h = __ldg(s1 + idx + hoff);
            const float o2  = __ldg(s2 + idx);
            const float o2v = __ldg(s2 + idx + voff);
            const float o2h = __ldg(s2 + idx + hoff);

            const float dv = o1 - o2;
            float f = dv * dv;
            float g, t;
            g = (o1 - o1v) * 100.0f;  t = fmaf(2.0f, g, -1.0f);  f = fmaf(t, t, f);
            g = (o1 - o1h) * 100.0f;  t = fmaf(2.0f, g, -1.0f);  f = fmaf(t, t, f);
            g = (o2 - o2v) * 100.0f;  t = fmaf(2.0f, g, -1.0f);  f = fmaf(t, t, f);
            g = (o2 - o2h) * 100.0f;  t = fmaf(2.0f, g, -1.0f);  f = fmaf(t, t, f);

            lacc = fmaf(w, f, lacc);
            lcnt += (act && bb == 0) ? 1u : 0u;   // count each pixel once
        }
    }

    // ---- warp reduce (float sum + count) ----
    #pragma unroll
    for (int o = 16; o > 0; o >>= 1) {
        lacc += __shfl_down_sync(0xffffffffu, lacc, o);
        lcnt += __shfl_down_sync(0xffffffffu, lcnt, o);
    }
    __shared__ float        sacc[WARPS_PER_BLK];
    __shared__ unsigned int scnt[WARPS_PER_BLK];
    if (lane == 0) { sacc[wid] = lacc; scnt[wid] = lcnt; }
    __syncthreads();
    if (wid == 0 && lane < WARPS_PER_BLK) {
        lacc = sacc[lane];
        lcnt = scnt[lane];
        #pragma unroll
        for (int o = WARPS_PER_BLK / 2; o > 0; o >>= 1) {
            lacc += __shfl_down_sync(0x0000000fu, lacc, o);
            lcnt += __shfl_down_sync(0x0000000fu, lcnt, o);
        }
        if (lane == 0) {
            atomicAdd(&g_acc, (double)lacc);
            atomicAdd(&g_nb, lcnt);
            __threadfence();
            const unsigned int old = atomicInc(&g_done, NBLOCKS - 1u);
            if (old == NBLOCKS - 1u) {         // last block finalizes + resets
                const double       tot = atomicAdd(&g_acc, 0.0);
                const unsigned int nb  = atomicAdd(&g_nb, 0u);
                out[0] = (float)(tot / (4.0 * (double)nb));
                g_acc = 0.0;
                g_nb  = 0u;
                __threadfence();
            }
        }
    }
}

extern "C" void kernel_launch(void* const* d_in, const int* in_sizes, int n_in,
                              void* d_out, int out_size)
{
    (void)in_sizes; (void)n_in; (void)out_size;
    const float* s1 = (const float*)d_in[0];
    const float* s2 = (const float*)d_in[1];
    float* out = (float*)d_out;
    ibl_kernel<<<NBLOCKS, WARPS_PER_BLK * 32>>>(s1, s2, out);
}